// round 1
// baseline (speedup 1.0000x reference)
#include <cuda_runtime.h>
#include <math.h>

#define Bn 2
#define Ln 2048
#define Dn 512
#define Vn 50257
#define NLn 12
#define Kn 5
#define An 128
#define Hn 128
#define BLn (Bn*Ln)          /* 4096 rows */
#define BLD (Bn*Ln*Dn)       /* 2,097,152 */

// ---------------- scratch (device globals: no allocation allowed) ----------
__device__ __align__(16) float g_x[BLD];
__device__ __align__(16) float g_xn[BLD];
__device__ __align__(16) float g_t1[BLD];
__device__ __align__(16) float g_xc[BLD];
__device__ __align__(16) float g_y[BLD];
__device__ __align__(16) float g_g1[BLD];
__device__ __align__(16) float g_g2[BLD];
__device__ __align__(16) float g_xs[Bn*Ln*An];
__device__ __align__(16) float g_hdn[Bn*Ln*Hn];

// ---------------- embedding + rope ----------------------------------------
__global__ void embed_rope_k(const int* __restrict__ tok,
                             const float* __restrict__ emb,
                             float* __restrict__ x) {
    int idx = blockIdx.x * blockDim.x + threadIdx.x;
    if (idx >= BLD) return;
    int d  = idx & (Dn - 1);
    int bl = idx >> 9;
    int l  = bl & (Ln - 1);
    int t  = tok[bl];
    const float* e = emb + (size_t)t * Dn;
    const int half = Dn / 2;
    int fi = (d < half) ? d : d - half;
    float invf = powf(10000.f, -(float)fi / (float)half);
    float ang  = (float)l * invf;
    float s, c;
    sincosf(ang, &s, &c);
    float v = e[d];
    float partner = (d < half) ? -e[d + half] : e[d - half];
    x[idx] = v * c + partner * s;
}

// ---------------- rmsnorm ---------------------------------------------------
__global__ void rmsnorm_k(const float* __restrict__ x,
                          const float* __restrict__ w,
                          float* __restrict__ o) {
    int row = blockIdx.x;                 // 0..BLn-1
    int t = threadIdx.x;                  // 256 threads
    const float* xr = x + (size_t)row * Dn;
    float a  = xr[t];
    float b2 = xr[t + 256];
    __shared__ float red[256];
    red[t] = a * a + b2 * b2;
    __syncthreads();
    for (int s = 128; s > 0; s >>= 1) {
        if (t < s) red[t] += red[t + s];
        __syncthreads();
    }
    float scale = rsqrtf(red[0] / (float)Dn + 1e-6f);
    o[(size_t)row * Dn + t]       = w[t]       * a  * scale;
    o[(size_t)row * Dn + t + 256] = w[t + 256] * b2 * scale;
}

// ---------------- depthwise dilated conv ------------------------------------
__global__ void dconv_k(const float* __restrict__ xn,
                        const float* __restrict__ dw,
                        const float* __restrict__ db,
                        float* __restrict__ o, int dil) {
    int idx = blockIdx.x * blockDim.x + threadIdx.x;
    if (idx >= BLD) return;
    int d  = idx & (Dn - 1);
    int bl = idx >> 9;
    int l  = bl & (Ln - 1);
    int b  = bl >> 11;
    float s = db[d];
#pragma unroll
    for (int k = 0; k < Kn; k++) {
        int t = l + (k - 2) * dil;
        if (t >= 0 && t < Ln)
            s += dw[d * Kn + k] * xn[(((size_t)(b * Ln + t)) << 9) + d];
    }
    o[idx] = s;
}

// ---------------- linear recurrence: warp-chunked parallel scan --------------
// h_t = alpha*h_{t-1} + beta*x_t, per (b, a) chain. 32 lanes x 64 steps.
__global__ void recur_k(const float* __restrict__ xn,
                        const float* __restrict__ alpha,
                        const float* __restrict__ beta,
                        float* __restrict__ xs) {
    int gw   = (blockIdx.x * blockDim.x + threadIdx.x) >> 5;  // 0..255
    int lane = threadIdx.x & 31;
    int b = gw >> 7;       // /A (A=128)
    int a = gw & 127;
    float al = alpha[a], be = beta[a];
    const float* xp = xn + ((size_t)(b * Ln + lane * 64) << 9) + a;
    float h = 0.f;
#pragma unroll 8
    for (int i = 0; i < 64; i++) h = fmaf(al, h, be * xp[(size_t)i << 9]);
    // al^64 via repeated squaring
    float p = al;
#pragma unroll
    for (int q = 0; q < 6; q++) p *= p;
    // inclusive segmented scan over (carry, factor)
    float c = h, f = p;
#pragma unroll
    for (int off = 1; off < 32; off <<= 1) {
        float cu = __shfl_up_sync(0xffffffffu, c, off);
        float fu = __shfl_up_sync(0xffffffffu, f, off);
        if (lane >= off) { c = fmaf(f, cu, c); f *= fu; }
    }
    float carry = __shfl_up_sync(0xffffffffu, c, 1);
    if (lane == 0) carry = 0.f;
    h = carry;
    float* op = xs + (size_t)(b * Ln + lane * 64) * An + a;
#pragma unroll 8
    for (int i = 0; i < 64; i++) {
        h = fmaf(al, h, be * xp[(size_t)i << 9]);
        op[i * An] = h;
    }
}

// ---------------- combine: y = xc + (d<A ? scan : xn) ------------------------
__global__ void combine_k(const float* __restrict__ xc,
                          const float* __restrict__ xs,
                          const float* __restrict__ xn,
                          float* __restrict__ y) {
    int idx = blockIdx.x * blockDim.x + threadIdx.x;
    if (idx >= BLD) return;
    int d  = idx & (Dn - 1);
    int bl = idx >> 9;
    float r = (d < An) ? xs[(size_t)bl * An + d] : xn[idx];
    y[idx] = xc[idx] + r;
}

// ---------------- gated unit: y += sigmoid(g1)*tanh(g2) ----------------------
__global__ void glu_k(const float* __restrict__ g1,
                      const float* __restrict__ g2,
                      float* __restrict__ y) {
    int idx = blockIdx.x * blockDim.x + threadIdx.x;
    if (idx >= BLD) return;
    float a = g1[idx], b = g2[idx];
    y[idx] += (1.f / (1.f + expf(-a))) * tanhf(b);
}

// ---------------- generic GEMM: C = epi(A[M,K] @ Bw[N,K]^T + bias) -----------
// EPI 0: store; EPI 1: exact gelu; EPI 2: C = C + add1 + v (residual fuse)
template <int BM, int BN, int TM, int TN, int EPI>
__global__ void gemm_k(const float* __restrict__ A,
                       const float* __restrict__ Bw,
                       const float* __restrict__ bias,
                       const float* __restrict__ add1,
                       float* __restrict__ C,
                       int M, int N, int K) {
    __shared__ float As[8][BM];
    __shared__ float Bs[8][BN];
    const int tid = threadIdx.x;   // 256 threads
    const int m0 = blockIdx.y * BM;
    const int n0 = blockIdx.x * BN;
    constexpr int TCN = BN / TN;
    const int tr = tid / TCN;
    const int tc = tid % TCN;
    float acc[TM][TN];
#pragma unroll
    for (int i = 0; i < TM; i++)
#pragma unroll
        for (int j = 0; j < TN; j++) acc[i][j] = 0.f;

    for (int k0 = 0; k0 < K; k0 += 8) {
#pragma unroll
        for (int i = tid; i < BM * 8; i += 256) {
            int r = i >> 3, kk = i & 7;
            As[kk][r] = A[(size_t)(m0 + r) * K + k0 + kk];
        }
#pragma unroll
        for (int i = tid; i < BN * 8; i += 256) {
            int r = i >> 3, kk = i & 7;
            int n = n0 + r;
            Bs[kk][r] = (n < N) ? Bw[(size_t)n * K + k0 + kk] : 0.f;
        }
        __syncthreads();
#pragma unroll
        for (int k = 0; k < 8; k++) {
            float ar[TM], br[TN];
#pragma unroll
            for (int i = 0; i < TM; i++) ar[i] = As[k][tr * TM + i];
#pragma unroll
            for (int j = 0; j < TN; j++) br[j] = Bs[k][tc * TN + j];
#pragma unroll
            for (int i = 0; i < TM; i++)
#pragma unroll
                for (int j = 0; j < TN; j++)
                    acc[i][j] = fmaf(ar[i], br[j], acc[i][j]);
        }
        __syncthreads();
    }
#pragma unroll
    for (int i = 0; i < TM; i++) {
        int m = m0 + tr * TM + i;
#pragma unroll
        for (int j = 0; j < TN; j++) {
            int n = n0 + tc * TN + j;
            if (n < N) {
                float v = acc[i][j] + (bias ? bias[n] : 0.f);
                size_t idx = (size_t)m * N + n;
                if (EPI == 0) {
                    C[idx] = v;
                } else if (EPI == 1) {
                    C[idx] = 0.5f * v * (1.f + erff(v * 0.70710678118654752f));
                } else {
                    C[idx] = C[idx] + add1[idx] + v;
                }
            }
        }
    }
}

// ---------------- host ------------------------------------------------------
extern "C" void kernel_launch(void* const* d_in, const int* in_sizes, int n_in,
                              void* d_out, int out_size) {
    const int*   tokens  = (const int*)  d_in[0];
    const float* emb     = (const float*)d_in[1];
    const float* norm_w  = (const float*)d_in[2];
    const float* dconv_w = (const float*)d_in[3];
    const float* dconv_b = (const float*)d_in[4];
    const float* pconv_w = (const float*)d_in[5];
    const float* pconv_b = (const float*)d_in[6];
    const float* alpha   = (const float*)d_in[7];
    const float* beta    = (const float*)d_in[8];
    const float* w1      = (const float*)d_in[9];
    const float* b1      = (const float*)d_in[10];
    const float* w2      = (const float*)d_in[11];
    const float* b2      = (const float*)d_in[12];
    const float* down_w  = (const float*)d_in[13];
    const float* down_b  = (const float*)d_in[14];
    const float* up_w    = (const float*)d_in[15];
    const float* up_b    = (const float*)d_in[16];
    const float* fnw     = (const float*)d_in[17];
    float* out = (float*)d_out;

    float *x, *xn, *t1, *xc, *y, *g1, *g2, *xs, *hdn;
    cudaGetSymbolAddress((void**)&x,   g_x);
    cudaGetSymbolAddress((void**)&xn,  g_xn);
    cudaGetSymbolAddress((void**)&t1,  g_t1);
    cudaGetSymbolAddress((void**)&xc,  g_xc);
    cudaGetSymbolAddress((void**)&y,   g_y);
    cudaGetSymbolAddress((void**)&g1,  g_g1);
    cudaGetSymbolAddress((void**)&g2,  g_g2);
    cudaGetSymbolAddress((void**)&xs,  g_xs);
    cudaGetSymbolAddress((void**)&hdn, g_hdn);

    const int egrid = (BLD + 255) / 256;

    embed_rope_k<<<egrid, 256>>>(tokens, emb, x);

    for (int i = 0; i < NLn; i++) {
        int dil = 1 << (i % 3);
        rmsnorm_k<<<BLn, 256>>>(x, norm_w + i * Dn, xn);
        dconv_k<<<egrid, 256>>>(xn, dconv_w + (size_t)i * Dn * Kn,
                                dconv_b + i * Dn, t1, dil);
        recur_k<<<32, 256>>>(xn, alpha + i * An, beta + i * An, xs);

        dim3 gpw(Dn / 128, BLn / 128);  // (4, 32)
        gemm_k<128, 128, 8, 8, 0><<<gpw, 256>>>(
            t1, pconv_w + (size_t)i * Dn * Dn, pconv_b + i * Dn, nullptr, xc,
            BLn, Dn, Dn);
        combine_k<<<egrid, 256>>>(xc, xs, xn, y);

        gemm_k<128, 128, 8, 8, 0><<<gpw, 256>>>(
            y, w1 + (size_t)i * Dn * Dn, b1 + i * Dn, nullptr, g1, BLn, Dn, Dn);
        gemm_k<128, 128, 8, 8, 0><<<gpw, 256>>>(
            y, w2 + (size_t)i * Dn * Dn, b2 + i * Dn, nullptr, g2, BLn, Dn, Dn);
        glu_k<<<egrid, 256>>>(g1, g2, y);

        dim3 gdn(Hn / 64, BLn / 64);    // (2, 64)
        gemm_k<64, 64, 4, 4, 1><<<gdn, 256>>>(
            y, down_w + (size_t)i * Hn * Dn, down_b + i * Hn, nullptr, hdn,
            BLn, Hn, Dn);
        // x_new = x_old + y + (hdn @ up^T + up_b)   (residual fused in epilogue)
        gemm_k<128, 128, 8, 8, 2><<<gpw, 256>>>(
            hdn, up_w + (size_t)i * Dn * Hn, up_b + i * Dn, y, x, BLn, Dn, Hn);
    }

    rmsnorm_k<<<BLn, 256>>>(x, fnw, xn);
    dim3 gl((Vn + 127) / 128, BLn / 128);  // (393, 32)
    gemm_k<128, 128, 8, 8, 0><<<gl, 256>>>(xn, emb, nullptr, nullptr, out,
                                           BLn, Vn, Dn);
}

// round 6
// speedup vs baseline: 5.0854x; 5.0854x over previous
#include <cuda_runtime.h>
#include <cstdint>
#include <math.h>

#define Bn 2
#define Ln 2048
#define Dn 512
#define Vn 50257
#define NLn 12
#define Kn 5
#define An 128
#define Hn 128
#define BLn (Bn*Ln)          /* 4096 rows */
#define BLD (Bn*Ln*Dn)       /* 2,097,152 */
#define CHK 128              /* recurrence chunks */
#define CLEN 16              /* tokens per chunk */

// ---------------- scratch (device globals: no allocation allowed) ----------
__device__ __align__(16) float g_x[BLD];
__device__ __align__(16) float g_xn[BLD];
__device__ __align__(16) float g_t1[BLD];
__device__ __align__(16) float g_xc[BLD];
__device__ __align__(16) float g_y[BLD];
__device__ __align__(16) float g_g1[BLD];
__device__ __align__(16) float g_g2[BLD];
__device__ __align__(16) float g_xs[Bn*Ln*An];
__device__ __align__(16) float g_hdn[Bn*Ln*Hn];
__device__ __align__(16) float g_pc [Bn*CHK*An];
__device__ __align__(16) float g_pcx[Bn*CHK*An];

__device__ __forceinline__ uint32_t tf32_bits(float x) {
    asm("cvt.rna.tf32.f32 %0, %0;" : "+f"(x));
    return __float_as_uint(x);
}

// ---------------- embedding + rope ----------------------------------------
__global__ void embed_rope_k(const int* __restrict__ tok,
                             const float* __restrict__ emb,
                             float* __restrict__ x) {
    int idx = blockIdx.x * blockDim.x + threadIdx.x;
    if (idx >= BLD) return;
    int d  = idx & (Dn - 1);
    int bl = idx >> 9;
    int l  = bl & (Ln - 1);
    int t  = tok[bl];
    const float* e = emb + (size_t)t * Dn;
    const int half = Dn / 2;
    int fi = (d < half) ? d : d - half;
    float invf = powf(10000.f, -(float)fi / (float)half);
    float ang  = (float)l * invf;
    float s, c;
    sincosf(ang, &s, &c);
    float v = e[d];
    float partner = (d < half) ? -e[d + half] : e[d - half];
    x[idx] = v * c + partner * s;
}

// ---------------- rmsnorm ---------------------------------------------------
__global__ void rmsnorm_k(const float* __restrict__ x,
                          const float* __restrict__ w,
                          float* __restrict__ o) {
    int row = blockIdx.x;
    int t = threadIdx.x;                  // 256 threads
    const float* xr = x + (size_t)row * Dn;
    float a  = xr[t];
    float b2 = xr[t + 256];
    __shared__ float red[256];
    red[t] = a * a + b2 * b2;
    __syncthreads();
    for (int s = 128; s > 0; s >>= 1) {
        if (t < s) red[t] += red[t + s];
        __syncthreads();
    }
    float scale = rsqrtf(red[0] / (float)Dn + 1e-6f);
    o[(size_t)row * Dn + t]       = w[t]       * a  * scale;
    o[(size_t)row * Dn + t + 256] = w[t + 256] * b2 * scale;
}

// ---------------- depthwise dilated conv ------------------------------------
__global__ void dconv_k(const float* __restrict__ xn,
                        const float* __restrict__ dw,
                        const float* __restrict__ db,
                        float* __restrict__ o, int dil) {
    int idx = blockIdx.x * blockDim.x + threadIdx.x;
    if (idx >= BLD) return;
    int d  = idx & (Dn - 1);
    int bl = idx >> 9;
    int l  = bl & (Ln - 1);
    int b  = bl >> 11;
    float s = db[d];
#pragma unroll
    for (int k = 0; k < Kn; k++) {
        int t = l + (k - 2) * dil;
        if (t >= 0 && t < Ln)
            s += dw[d * Kn + k] * xn[(((size_t)(b * Ln + t)) << 9) + d];
    }
    o[idx] = s;
}

// ---------------- recurrence: 3-phase chunked scan ---------------------------
__global__ void recur_part_k(const float* __restrict__ xn,
                             const float* __restrict__ alpha,
                             const float* __restrict__ beta,
                             float* __restrict__ pc) {
    int ch = blockIdx.x & (CHK - 1);
    int b  = blockIdx.x >> 7;
    int a  = threadIdx.x;                 // 128
    float al = alpha[a], be = beta[a];
    const float* xp = xn + ((size_t)(b * Ln + ch * CLEN) << 9) + a;
    float h = 0.f;
#pragma unroll
    for (int i = 0; i < CLEN; i++) h = fmaf(al, h, be * xp[(size_t)i << 9]);
    pc[(b * CHK + ch) * An + a] = h;
}

__global__ void recur_scan_k(const float* __restrict__ pc,
                             const float* __restrict__ alpha,
                             float* __restrict__ pcx) {
    int t = threadIdx.x;                  // 256
    int b = t >> 7;
    int a = t & 127;
    float al = alpha[a];
    float f = al;
#pragma unroll
    for (int q = 0; q < 4; q++) f *= f;   // al^16
    float carry = 0.f;
    for (int ch = 0; ch < CHK; ch++) {
        int idx = (b * CHK + ch) * An + a;
        pcx[idx] = carry;
        carry = fmaf(f, carry, pc[idx]);
    }
}

__global__ void recur_apply_k(const float* __restrict__ xn,
                              const float* __restrict__ alpha,
                              const float* __restrict__ beta,
                              const float* __restrict__ pcx,
                              float* __restrict__ xs) {
    int ch = blockIdx.x & (CHK - 1);
    int b  = blockIdx.x >> 7;
    int a  = threadIdx.x;
    float al = alpha[a], be = beta[a];
    float h = pcx[(b * CHK + ch) * An + a];
    const float* xp = xn + ((size_t)(b * Ln + ch * CLEN) << 9) + a;
    float* op = xs + (size_t)(b * Ln + ch * CLEN) * An + a;
#pragma unroll
    for (int i = 0; i < CLEN; i++) {
        h = fmaf(al, h, be * xp[(size_t)i << 9]);
        op[i * An] = h;
    }
}

// ---------------- combine: y = xc + (d<A ? scan : xn) ------------------------
__global__ void combine_k(const float* __restrict__ xc,
                          const float* __restrict__ xs,
                          const float* __restrict__ xn,
                          float* __restrict__ y) {
    int idx = blockIdx.x * blockDim.x + threadIdx.x;
    if (idx >= BLD) return;
    int d  = idx & (Dn - 1);
    int bl = idx >> 9;
    float r = (d < An) ? xs[(size_t)bl * An + d] : xn[idx];
    y[idx] = xc[idx] + r;
}

// ---------------- gated unit: y += sigmoid(g1)*tanh(g2) ----------------------
__global__ void glu_k(const float* __restrict__ g1,
                      const float* __restrict__ g2,
                      float* __restrict__ y) {
    int idx = blockIdx.x * blockDim.x + threadIdx.x;
    if (idx >= BLD) return;
    float a = g1[idx], b = g2[idx];
    y[idx] += (1.f / (1.f + expf(-a))) * tanhf(b);
}

// ---------------- tensor-core GEMM: C = epi(A[M,K] @ Bw[N,K]^T + bias) -------
// tf32 mma.sync m16n8k8, 128x128 tile, BK=16, cp.async 2-stage pipeline.
// Operands rna-rounded to tf32 IN REGISTERS.
// EPI 0: store; EPI 1: exact gelu; EPI 2: C = C + add1 + v
__device__ __forceinline__ void cp16(uint32_t dst, const void* src, bool pred) {
    asm volatile("cp.async.cg.shared.global [%0], [%1], 16, %2;\n"
                 :: "r"(dst), "l"(src), "r"(pred ? 16 : 0));
}

template <int EPI>
__global__ void __launch_bounds__(256)
gemm_tc(const float* __restrict__ A,
        const float* __restrict__ Bw,
        const float* __restrict__ bias,
        const float* __restrict__ add1,
        float* __restrict__ C,
        int M, int N, int K) {
    __shared__ float As[2][128][20];
    __shared__ float Bs[2][128][20];

    const int tid  = threadIdx.x;
    const int m0   = blockIdx.y * 128;
    const int n0   = blockIdx.x * 128;
    const int wid  = tid >> 5;
    const int lane = tid & 31;
    const int wr   = wid >> 2;          // 0..1
    const int wc   = wid & 3;           // 0..3
    const int gid  = lane >> 2;
    const int tig  = lane & 3;
    const int mb   = wr * 64;
    const int nb   = wc * 32;

    const int lr = tid >> 2;            // 0..63
    const int lc = (tid & 3) * 4;       // 0,4,8,12

    float acc[4][4][4];
#pragma unroll
    for (int mt = 0; mt < 4; mt++)
#pragma unroll
        for (int nt = 0; nt < 4; nt++)
#pragma unroll
            for (int r = 0; r < 4; r++) acc[mt][nt][r] = 0.f;

    const int KT = K >> 4;

    auto issue = [&](int kt, int s) {
        int k0 = kt << 4;
        const float* ag = A + (size_t)(m0 + lr) * K + k0 + lc;
        cp16(__cvta_generic_to_shared(&As[s][lr][lc]),      ag,          true);
        cp16(__cvta_generic_to_shared(&As[s][lr + 64][lc]), ag + (size_t)64 * K, true);
        int nrow0 = n0 + lr, nrow1 = n0 + lr + 64;
        const float* bg0 = Bw + (size_t)(nrow0 < N ? nrow0 : 0) * K + k0 + lc;
        const float* bg1 = Bw + (size_t)(nrow1 < N ? nrow1 : 0) * K + k0 + lc;
        cp16(__cvta_generic_to_shared(&Bs[s][lr][lc]),      bg0, nrow0 < N);
        cp16(__cvta_generic_to_shared(&Bs[s][lr + 64][lc]), bg1, nrow1 < N);
    };

    issue(0, 0);
    asm volatile("cp.async.commit_group;\n");

    for (int kt = 0; kt < KT; kt++) {
        int s = kt & 1;
        if (kt + 1 < KT) {
            issue(kt + 1, s ^ 1);
            asm volatile("cp.async.commit_group;\n");
            asm volatile("cp.async.wait_group 1;\n");
        } else {
            asm volatile("cp.async.wait_group 0;\n");
        }
        __syncthreads();

#pragma unroll
        for (int k8 = 0; k8 < 2; k8++) {
            const int kk = k8 * 8;
            uint32_t a[4][4], b[4][2];
#pragma unroll
            for (int mt = 0; mt < 4; mt++) {
                int r = mb + mt * 16 + gid;
                a[mt][0] = tf32_bits(As[s][r][kk + tig]);
                a[mt][1] = tf32_bits(As[s][r + 8][kk + tig]);
                a[mt][2] = tf32_bits(As[s][r][kk + tig + 4]);
                a[mt][3] = tf32_bits(As[s][r + 8][kk + tig + 4]);
            }
#pragma unroll
            for (int nt = 0; nt < 4; nt++) {
                int c = nb + nt * 8 + gid;
                b[nt][0] = tf32_bits(Bs[s][c][kk + tig]);
                b[nt][1] = tf32_bits(Bs[s][c][kk + tig + 4]);
            }
#pragma unroll
            for (int mt = 0; mt < 4; mt++)
#pragma unroll
                for (int nt = 0; nt < 4; nt++) {
                    asm volatile(
                        "mma.sync.aligned.m16n8k8.row.col.f32.tf32.tf32.f32 "
                        "{%0,%1,%2,%3}, {%4,%5,%6,%7}, {%8,%9}, {%0,%1,%2,%3};\n"
                        : "+f"(acc[mt][nt][0]), "+f"(acc[mt][nt][1]),
                          "+f"(acc[mt][nt][2]), "+f"(acc[mt][nt][3])
                        : "r"(a[mt][0]), "r"(a[mt][1]), "r"(a[mt][2]), "r"(a[mt][3]),
                          "r"(b[nt][0]), "r"(b[nt][1]));
                }
        }
        __syncthreads();
    }

    // epilogue
#pragma unroll
    for (int mt = 0; mt < 4; mt++) {
        int row0 = m0 + mb + mt * 16 + gid;
#pragma unroll
        for (int nt = 0; nt < 4; nt++) {
            int col0 = n0 + nb + nt * 8 + tig * 2;
#pragma unroll
            for (int half = 0; half < 2; half++) {
                int rr = row0 + half * 8;
#pragma unroll
                for (int cc = 0; cc < 2; cc++) {
                    int col = col0 + cc;
                    if (col < N) {
                        float v = acc[mt][nt][half * 2 + cc] + (bias ? bias[col] : 0.f);
                        size_t idx = (size_t)rr * N + col;
                        if (EPI == 0) {
                            C[idx] = v;
                        } else if (EPI == 1) {
                            C[idx] = 0.5f * v * (1.f + erff(v * 0.70710678118654752f));
                        } else {
                            C[idx] = C[idx] + add1[idx] + v;
                        }
                    }
                }
            }
        }
    }
}

// ---------------- host ------------------------------------------------------
extern "C" void kernel_launch(void* const* d_in, const int* in_sizes, int n_in,
                              void* d_out, int out_size) {
    const int*   tokens  = (const int*)  d_in[0];
    const float* emb     = (const float*)d_in[1];
    const float* norm_w  = (const float*)d_in[2];
    const float* dconv_w = (const float*)d_in[3];
    const float* dconv_b = (const float*)d_in[4];
    const float* pconv_w = (const float*)d_in[5];
    const float* pconv_b = (const float*)d_in[6];
    const float* alpha   = (const float*)d_in[7];
    const float* beta    = (const float*)d_in[8];
    const float* w1      = (const float*)d_in[9];
    const float* b1      = (const float*)d_in[10];
    const float* w2      = (const float*)d_in[11];
    const float* b2      = (const float*)d_in[12];
    const float* down_w  = (const float*)d_in[13];
    const float* down_b  = (const float*)d_in[14];
    const float* up_w    = (const float*)d_in[15];
    const float* up_b    = (const float*)d_in[16];
    const float* fnw     = (const float*)d_in[17];
    float* out = (float*)d_out;

    float *x, *xn, *t1, *xc, *y, *g1, *g2, *xs, *hdn, *pc, *pcx;
    cudaGetSymbolAddress((void**)&x,   g_x);
    cudaGetSymbolAddress((void**)&xn,  g_xn);
    cudaGetSymbolAddress((void**)&t1,  g_t1);
    cudaGetSymbolAddress((void**)&xc,  g_xc);
    cudaGetSymbolAddress((void**)&y,   g_y);
    cudaGetSymbolAddress((void**)&g1,  g_g1);
    cudaGetSymbolAddress((void**)&g2,  g_g2);
    cudaGetSymbolAddress((void**)&xs,  g_xs);
    cudaGetSymbolAddress((void**)&hdn, g_hdn);
    cudaGetSymbolAddress((void**)&pc,  g_pc);
    cudaGetSymbolAddress((void**)&pcx, g_pcx);

    const int egrid = (BLD + 255) / 256;

    embed_rope_k<<<egrid, 256>>>(tokens, emb, x);

    for (int i = 0; i < NLn; i++) {
        int dil = 1 << (i % 3);
        rmsnorm_k<<<BLn, 256>>>(x, norm_w + i * Dn, xn);
        dconv_k<<<egrid, 256>>>(xn, dconv_w + (size_t)i * Dn * Kn,
                                dconv_b + i * Dn, t1, dil);
        recur_part_k<<<Bn * CHK, An>>>(xn, alpha + i * An, beta + i * An, pc);
        recur_scan_k<<<1, 256>>>(pc, alpha + i * An, pcx);
        recur_apply_k<<<Bn * CHK, An>>>(xn, alpha + i * An, beta + i * An, pcx, xs);

        dim3 gpw(Dn / 128, BLn / 128);  // (4, 32)
        gemm_tc<0><<<gpw, 256>>>(t1, pconv_w + (size_t)i * Dn * Dn,
                                 pconv_b + i * Dn, nullptr, xc, BLn, Dn, Dn);
        combine_k<<<egrid, 256>>>(xc, xs, xn, y);

        gemm_tc<0><<<gpw, 256>>>(y, w1 + (size_t)i * Dn * Dn,
                                 b1 + i * Dn, nullptr, g1, BLn, Dn, Dn);
        gemm_tc<0><<<gpw, 256>>>(y, w2 + (size_t)i * Dn * Dn,
                                 b2 + i * Dn, nullptr, g2, BLn, Dn, Dn);
        glu_k<<<egrid, 256>>>(g1, g2, y);

        dim3 gdn(Hn / 128, BLn / 128);  // (1, 32)
        gemm_tc<1><<<gdn, 256>>>(y, down_w + (size_t)i * Hn * Dn,
                                 down_b + i * Hn, nullptr, hdn, BLn, Hn, Dn);
        dim3 gup(Dn / 128, BLn / 128);
        gemm_tc<2><<<gup, 256>>>(hdn, up_w + (size_t)i * Dn * Hn,
                                 up_b + i * Dn, y, x, BLn, Dn, Hn);
    }

    rmsnorm_k<<<BLn, 256>>>(x, fnw, xn);
    dim3 gl((Vn + 127) / 128, BLn / 128);  // (393, 32)
    gemm_tc<0><<<gl, 256>>>(xn, emb, nullptr, nullptr, out, BLn, Vn, Dn);
}